// round 1
// baseline (speedup 1.0000x reference)
#include <cuda_runtime.h>
#include <cuda_bf16.h>
#include <math.h>

// Problem constants (fixed shapes)
#define NN 768          // nodes
#define EE 24576        // edges
#define DD 1024         // feature dim

// ---------------- scratch (static device globals; no allocation) ----------------
__device__ __align__(128) float g_NP[NN * 4 * DD];     // [vj@Wr_s | vj@Wr_o | vj@Ws_v | vj@Wo_v]
__device__ __align__(128) float g_rel[EE * DD];
__device__ __align__(128) float g_ts[EE * DD];
__device__ __align__(128) float g_to[EE * DD];
__device__ __align__(128) float g_ctx[NN * DD];
__device__ __align__(128) float g_logits[EE];
__device__ __align__(128) float g_wS[EE];
__device__ __align__(128) float g_wO[EE];
__device__ unsigned g_maxS[NN], g_maxO[NN];
__device__ float g_sumS[NN], g_sumO[NN];
__device__ int g_degS[NN], g_degO[NN], g_baseS[NN], g_baseO[NN], g_curO[NN];
__device__ int g_permO[EE];

// ---------------- helpers ----------------
__device__ __forceinline__ unsigned f2tf(float f) {
    unsigned r;
    asm("cvt.rna.tf32.f32 %0, %1;" : "=r"(r) : "f"(f));
    return r;
}

__device__ __forceinline__ void mma_tf32(float c[4], unsigned a0, unsigned a1, unsigned a2, unsigned a3,
                                         unsigned b0, unsigned b1) {
    asm volatile(
        "mma.sync.aligned.m16n8k8.row.col.f32.tf32.tf32.f32 "
        "{%0,%1,%2,%3},{%4,%5,%6,%7},{%8,%9},{%0,%1,%2,%3};"
        : "+f"(c[0]), "+f"(c[1]), "+f"(c[2]), "+f"(c[3])
        : "r"(a0), "r"(a1), "r"(a2), "r"(a3), "r"(b0), "r"(b1));
}

__device__ __forceinline__ unsigned fkey(float f) {
    unsigned u = __float_as_uint(f);
    return (u & 0x80000000u) ? ~u : (u | 0x80000000u);
}
__device__ __forceinline__ float funkey(unsigned k) {
    return (k & 0x80000000u) ? __uint_as_float(k ^ 0x80000000u) : __uint_as_float(~k);
}

// ---------------- tf32 GEMM with fused epilogues ----------------
// C[M,1024] = A[M,1024] @ B[1024,1024] (both row-major), M multiple of 128.
// mode 0: write to g_NP[:, coloff:coloff+1024]
// mode 1: rel  = C + NP[sbj[m]][c] + NP[obj[m]][1024+c] + bias[c]      -> g_rel
// mode 2: ts   = C + NP[sbj[m]][2048+c] + bias[c]                      -> g_ts   (A = g_rel)
// mode 3: to   = C + NP[obj[m]][3072+c] + bias[c]                      -> g_to   (A = g_rel)
// mode 4: vjout= vf[m][c] + C + (deg[m]>0 ? bias[c] : 0)               -> out_ext (A = g_ctx)
__global__ void gemm_tf32(int mode,
                          const float* __restrict__ A_ext,
                          const float* __restrict__ B,
                          float* __restrict__ out_ext,
                          int coloff,
                          const float* __restrict__ bias,
                          const int* __restrict__ sbj,
                          const int* __restrict__ obj,
                          const float* __restrict__ vf) {
    __shared__ float As[128 * 36];
    __shared__ float Bs[32 * 132];

    const float* A = A_ext;
    if (mode == 2 || mode == 3) A = g_rel;
    if (mode == 4) A = g_ctx;

    int tid = threadIdx.x;
    int lane = tid & 31;
    int warp = tid >> 5;
    int wm = (warp & 3) * 32;
    int wn = (warp >> 2) * 64;
    int bm = blockIdx.y * 128;
    int bn = blockIdx.x * 128;

    float acc[2][8][4];
#pragma unroll
    for (int a = 0; a < 2; a++)
#pragma unroll
        for (int b = 0; b < 8; b++)
#pragma unroll
            for (int c = 0; c < 4; c++) acc[a][b][c] = 0.f;

    for (int kt = 0; kt < DD; kt += 32) {
#pragma unroll
        for (int p = 0; p < 4; p++) {
            int r = p * 32 + (tid >> 3);
            int c = (tid & 7) * 4;
            float4 v = *(const float4*)(A + (size_t)(bm + r) * DD + kt + c);
            *(float4*)(As + r * 36 + c) = v;
        }
#pragma unroll
        for (int p = 0; p < 4; p++) {
            int r = tid >> 3;
            int c = p * 32 + (tid & 7) * 4;
            float4 v = *(const float4*)(B + (size_t)(kt + r) * DD + bn + c);
            *(float4*)(Bs + r * 132 + c) = v;
        }
        __syncthreads();
#pragma unroll
        for (int kk = 0; kk < 4; kk++) {
            int k0 = kk * 8;
            unsigned af[2][4], bf[8][2];
#pragma unroll
            for (int mt = 0; mt < 2; mt++) {
                int r = wm + mt * 16 + (lane >> 2);
                int c = k0 + (lane & 3);
                af[mt][0] = f2tf(As[r * 36 + c]);
                af[mt][1] = f2tf(As[(r + 8) * 36 + c]);
                af[mt][2] = f2tf(As[r * 36 + c + 4]);
                af[mt][3] = f2tf(As[(r + 8) * 36 + c + 4]);
            }
#pragma unroll
            for (int nt = 0; nt < 8; nt++) {
                int cc = wn + nt * 8 + (lane >> 2);
                int rr = k0 + (lane & 3);
                bf[nt][0] = f2tf(Bs[rr * 132 + cc]);
                bf[nt][1] = f2tf(Bs[(rr + 4) * 132 + cc]);
            }
#pragma unroll
            for (int mt = 0; mt < 2; mt++)
#pragma unroll
                for (int nt = 0; nt < 8; nt++)
                    mma_tf32(acc[mt][nt], af[mt][0], af[mt][1], af[mt][2], af[mt][3],
                             bf[nt][0], bf[nt][1]);
        }
        __syncthreads();
    }

    // epilogue
#pragma unroll
    for (int mt = 0; mt < 2; mt++) {
#pragma unroll
        for (int half = 0; half < 2; half++) {
            int r = bm + wm + mt * 16 + (lane >> 2) + half * 8;
            if (mode == 0) {
                float* outr = g_NP + (size_t)r * (4 * DD) + coloff;
#pragma unroll
                for (int nt = 0; nt < 8; nt++) {
                    int c = bn + wn + nt * 8 + (lane & 3) * 2;
                    float2 v;
                    v.x = acc[mt][nt][half * 2 + 0];
                    v.y = acc[mt][nt][half * 2 + 1];
                    *(float2*)(outr + c) = v;
                }
            } else if (mode == 1) {
                const float* npa = g_NP + (size_t)sbj[r] * (4 * DD);
                const float* npb = g_NP + (size_t)obj[r] * (4 * DD) + DD;
                float* outr = g_rel + (size_t)r * DD;
#pragma unroll
                for (int nt = 0; nt < 8; nt++) {
                    int c = bn + wn + nt * 8 + (lane & 3) * 2;
                    float2 v;
                    v.x = acc[mt][nt][half * 2 + 0] + npa[c] + npb[c] + bias[c];
                    v.y = acc[mt][nt][half * 2 + 1] + npa[c + 1] + npb[c + 1] + bias[c + 1];
                    *(float2*)(outr + c) = v;
                }
            } else if (mode == 2) {
                const float* npa = g_NP + (size_t)sbj[r] * (4 * DD) + 2 * DD;
                float* outr = g_ts + (size_t)r * DD;
#pragma unroll
                for (int nt = 0; nt < 8; nt++) {
                    int c = bn + wn + nt * 8 + (lane & 3) * 2;
                    float2 v;
                    v.x = acc[mt][nt][half * 2 + 0] + npa[c] + bias[c];
                    v.y = acc[mt][nt][half * 2 + 1] + npa[c + 1] + bias[c + 1];
                    *(float2*)(outr + c) = v;
                }
            } else if (mode == 3) {
                const float* npa = g_NP + (size_t)obj[r] * (4 * DD) + 3 * DD;
                float* outr = g_to + (size_t)r * DD;
#pragma unroll
                for (int nt = 0; nt < 8; nt++) {
                    int c = bn + wn + nt * 8 + (lane & 3) * 2;
                    float2 v;
                    v.x = acc[mt][nt][half * 2 + 0] + npa[c] + bias[c];
                    v.y = acc[mt][nt][half * 2 + 1] + npa[c + 1] + bias[c + 1];
                    *(float2*)(outr + c) = v;
                }
            } else {  // mode 4
                bool inv = (g_degS[r] + g_degO[r]) > 0;
                const float* vfr = vf + (size_t)r * DD;
                float* outr = out_ext + (size_t)r * DD;
#pragma unroll
                for (int nt = 0; nt < 8; nt++) {
                    int c = bn + wn + nt * 8 + (lane & 3) * 2;
                    float2 v;
                    v.x = vfr[c] + acc[mt][nt][half * 2 + 0] + (inv ? bias[c] : 0.f);
                    v.y = vfr[c + 1] + acc[mt][nt][half * 2 + 1] + (inv ? bias[c + 1] : 0.f);
                    *(float2*)(outr + c) = v;
                }
            }
        }
    }
}

// ---------------- small kernels ----------------
__global__ void k_init() {
    int i = blockIdx.x * blockDim.x + threadIdx.x;
    if (i < NN * DD) g_ctx[i] = 0.f;
    if (i < EE) g_logits[i] = 0.f;
    if (i < NN) {
        g_sumS[i] = 0.f; g_sumO[i] = 0.f;
        g_maxS[i] = 0u; g_maxO[i] = 0u;
        g_degS[i] = 0; g_degO[i] = 0;
    }
}

__global__ void k_hist(const int* __restrict__ sbj, const int* __restrict__ obj) {
    int e = blockIdx.x * blockDim.x + threadIdx.x;
    if (e < EE) {
        atomicAdd(&g_degS[sbj[e]], 1);
        atomicAdd(&g_degO[obj[e]], 1);
    }
}

__global__ void k_scan() {
    if (threadIdx.x == 0) {
        int s = 0, o = 0;
        for (int n = 0; n < NN; n++) {
            g_baseS[n] = s; s += g_degS[n];
            g_baseO[n] = o; g_curO[n] = o; o += g_degO[n];
        }
    }
}

__global__ void k_scatter(const int* __restrict__ obj) {
    int e = blockIdx.x * blockDim.x + threadIdx.x;
    if (e < EE) {
        int p = atomicAdd(&g_curO[obj[e]], 1);
        g_permO[p] = e;
    }
}

__global__ void k_dot() {
    int e = blockIdx.x * 8 + (threadIdx.x >> 5);
    int lane = threadIdx.x & 31;
    if (e >= EE) return;
    const float4* t4 = (const float4*)(g_ts + (size_t)e * DD);
    const float4* o4 = (const float4*)(g_to + (size_t)e * DD);
    float s = 0.f;
#pragma unroll
    for (int i = 0; i < 8; i++) {
        float4 a = t4[i * 32 + lane];
        float4 b = o4[i * 32 + lane];
        s += a.x * b.x + a.y * b.y + a.z * b.z + a.w * b.w;
    }
#pragma unroll
    for (int off = 16; off > 0; off >>= 1) s += __shfl_xor_sync(0xFFFFFFFF, s, off);
    if (lane == 0) g_logits[e] = s * 0.03125f;  // 1/sqrt(1024)
}

__global__ void k_max(const int* __restrict__ sbj, const int* __restrict__ obj) {
    int e = blockIdx.x * blockDim.x + threadIdx.x;
    if (e < EE) {
        unsigned k = fkey(g_logits[e]);
        atomicMax(&g_maxS[sbj[e]], k);
        atomicMax(&g_maxO[obj[e]], k);
    }
}

__global__ void k_exp(const int* __restrict__ sbj, const int* __restrict__ obj) {
    int e = blockIdx.x * blockDim.x + threadIdx.x;
    if (e < EE) {
        float l = g_logits[e];
        float es = expf(l - funkey(g_maxS[sbj[e]]));
        float eo = expf(l - funkey(g_maxO[obj[e]]));
        g_wS[e] = es;
        g_wO[e] = eo;
        atomicAdd(&g_sumS[sbj[e]], es);
        atomicAdd(&g_sumO[obj[e]], eo);
    }
}

__global__ void k_norm(const int* __restrict__ sbj, const int* __restrict__ obj) {
    int e = blockIdx.x * blockDim.x + threadIdx.x;
    if (e < EE) {
        g_wS[e] /= g_sumS[sbj[e]];
        g_wO[e] /= g_sumO[obj[e]];
    }
}

__global__ void k_ctxS(const int* __restrict__ obj, const float* __restrict__ vf) {
    int n = blockIdx.x;
    int t = threadIdx.x;
    int beg = g_baseS[n], cnt = g_degS[n];
    if (cnt == 0) return;
    const float4* vf4 = (const float4*)vf;
    float4 acc = make_float4(0.f, 0.f, 0.f, 0.f);
    for (int i = 0; i < cnt; i++) {
        int e = beg + i;
        float w = g_wS[e];
        float4 v = vf4[(size_t)obj[e] * 256 + t];
        acc.x += w * v.x; acc.y += w * v.y; acc.z += w * v.z; acc.w += w * v.w;
    }
    ((float4*)g_ctx)[(size_t)n * 256 + t] = acc;
}

__global__ void k_ctxO(const int* __restrict__ sbj, const float* __restrict__ vf) {
    int n = blockIdx.x;
    int t = threadIdx.x;
    int beg = g_baseO[n], cnt = g_degO[n];
    if (cnt == 0) return;
    const float4* vf4 = (const float4*)vf;
    float4 acc = make_float4(0.f, 0.f, 0.f, 0.f);
    for (int i = 0; i < cnt; i++) {
        int e = g_permO[beg + i];
        float w = g_wO[e];
        float4 v = vf4[(size_t)sbj[e] * 256 + t];
        acc.x += w * v.x; acc.y += w * v.y; acc.z += w * v.z; acc.w += w * v.w;
    }
    float4* c4 = (float4*)g_ctx;
    float4 old = c4[(size_t)n * 256 + t];
    old.x += acc.x; old.y += acc.y; old.z += acc.z; old.w += acc.w;
    c4[(size_t)n * 256 + t] = old;
}

// ---------------- launch ----------------
extern "C" void kernel_launch(void* const* d_in, const int* in_sizes, int n_in,
                              void* d_out, int out_size) {
    const float* vf    = (const float*)d_in[0];   // visual_feat [N,D]
    const float* R     = (const float*)d_in[1];   // rel_visual_feat [E,D]
    const float* W_rel = (const float*)d_in[2];   // [3D,D]
    const float* b_rel = (const float*)d_in[3];
    const float* W_sbj = (const float*)d_in[4];   // [2D,D]
    const float* b_sbj = (const float*)d_in[5];
    const float* W_obj = (const float*)d_in[6];   // [2D,D]
    const float* b_obj = (const float*)d_in[7];
    const float* W_ctx = (const float*)d_in[8];   // [D,D]
    const float* b_ctx = (const float*)d_in[9];
    const int* sbj     = (const int*)d_in[10];
    const int* obj     = (const int*)d_in[11];

    float* out = (float*)d_out;

    // passthrough: rel_visual_feat -> out[0 : E*D]
    cudaMemcpyAsync(out, R, (size_t)EE * DD * sizeof(float), cudaMemcpyDeviceToDevice);

    // init / graph prep
    k_init<<<(NN * DD + 255) / 256, 256>>>();
    k_hist<<<(EE + 255) / 256, 256>>>(sbj, obj);
    k_scan<<<1, 32>>>();
    k_scatter<<<(EE + 255) / 256, 256>>>(obj);

    dim3 gNode(DD / 128, NN / 128);   // (8, 6)
    dim3 gEdge(DD / 128, EE / 128);   // (8, 192)

    // node projections NP = vf @ [Wr_s | Wr_o | Ws_v | Wo_v]
    gemm_tf32<<<gNode, 256>>>(0, vf, W_rel,            nullptr, 0,        nullptr, nullptr, nullptr, nullptr);
    gemm_tf32<<<gNode, 256>>>(0, vf, W_rel + DD * DD,  nullptr, DD,       nullptr, nullptr, nullptr, nullptr);
    gemm_tf32<<<gNode, 256>>>(0, vf, W_sbj,            nullptr, 2 * DD,   nullptr, nullptr, nullptr, nullptr);
    gemm_tf32<<<gNode, 256>>>(0, vf, W_obj,            nullptr, 3 * DD,   nullptr, nullptr, nullptr, nullptr);

    // rel = R @ Wr_r + NP_s[sbj] + NP_o[obj] + b_rel
    gemm_tf32<<<gEdge, 256>>>(1, R, W_rel + 2 * DD * DD, nullptr, 0, b_rel, sbj, obj, nullptr);
    // ts = rel @ Ws_r + NP_sv[sbj] + b_sbj ; to = rel @ Wo_r + NP_ov[obj] + b_obj
    gemm_tf32<<<gEdge, 256>>>(2, nullptr, W_sbj + DD * DD, nullptr, 0, b_sbj, sbj, obj, nullptr);
    gemm_tf32<<<gEdge, 256>>>(3, nullptr, W_obj + DD * DD, nullptr, 0, b_obj, sbj, obj, nullptr);

    // logits + dual edge-softmax
    k_dot<<<EE / 8, 256>>>();
    k_max<<<(EE + 255) / 256, 256>>>(sbj, obj);
    k_exp<<<(EE + 255) / 256, 256>>>(sbj, obj);
    k_norm<<<(EE + 255) / 256, 256>>>(sbj, obj);

    // ctx aggregation
    k_ctxS<<<NN, 256>>>(obj, vf);
    k_ctxO<<<NN, 256>>>(sbj, vf);

    // vj_out = vf + ctx @ W_ctx + b_ctx (involved), else vf
    gemm_tf32<<<gNode, 256>>>(4, nullptr, W_ctx, out + (size_t)EE * DD, 0, b_ctx, sbj, obj, vf);

    (void)in_sizes; (void)n_in; (void)out_size;
}

// round 2
// speedup vs baseline: 1.3659x; 1.3659x over previous
#include <cuda_runtime.h>
#include <cuda_bf16.h>
#include <math.h>

#define NN 768
#define EE 24576
#define DD 1024

// ---------------- scratch ----------------
__device__ __align__(128) float g_Hs[DD * DD];
__device__ __align__(128) float g_Ho[DD * DD];
__device__ __align__(128) float g_K [DD * DD];
__device__ __align__(128) float g_M [4 * DD * DD];   // M1..M4
__device__ __align__(128) float g_T [4 * NN * DD];   // Ts, Us, To, Uo
__device__ __align__(128) float g_S1[NN * DD];
__device__ __align__(128) float g_S2[NN * DD];
__device__ __align__(128) float g_G [NN * NN];
__device__ __align__(128) float g_ctx[NN * DD];
__device__ float g_cs[DD], g_co[DD], g_c3[DD];
__device__ float g_d1[NN], g_d2[NN];
__device__ __align__(128) float g_logits[EE];
__device__ __align__(128) float g_wS[EE];
__device__ __align__(128) float g_wO[EE];
__device__ unsigned g_maxS[NN], g_maxO[NN];
__device__ float g_sumS[NN], g_sumO[NN];
__device__ int g_degS[NN], g_degO[NN], g_baseS[NN], g_baseO[NN], g_curO[NN];
__device__ int g_permO[EE];

// ---------------- helpers ----------------
__device__ __forceinline__ unsigned f2tf(float f) {
    unsigned r;
    asm("cvt.rna.tf32.f32 %0, %1;" : "=r"(r) : "f"(f));
    return r;
}
__device__ __forceinline__ void mma_tf32(float c[4], unsigned a0, unsigned a1, unsigned a2, unsigned a3,
                                         unsigned b0, unsigned b1) {
    asm volatile(
        "mma.sync.aligned.m16n8k8.row.col.f32.tf32.tf32.f32 "
        "{%0,%1,%2,%3},{%4,%5,%6,%7},{%8,%9},{%0,%1,%2,%3};"
        : "+f"(c[0]), "+f"(c[1]), "+f"(c[2]), "+f"(c[3])
        : "r"(a0), "r"(a1), "r"(a2), "r"(a3), "r"(b0), "r"(b1));
}
__device__ __forceinline__ unsigned fkey(float f) {
    unsigned u = __float_as_uint(f);
    return (u & 0x80000000u) ? ~u : (u | 0x80000000u);
}
__device__ __forceinline__ float funkey(unsigned k) {
    return (k & 0x80000000u) ? __uint_as_float(k ^ 0x80000000u) : __uint_as_float(~k);
}

// ---------------- shared tf32 mainloop (128x128 tile, K=1024) ----------------
// TB=false: C = A[M,1024] @ B[1024,1024]   (B row-major, NN)
// TB=true : C = A[M,1024] @ B^T, B[N,1024] (NT)
template<bool TB>
__device__ __forceinline__ void run_mainloop(const float* __restrict__ A,
                                             const float* __restrict__ B,
                                             int bm, int bn,
                                             float (&acc)[2][8][4],
                                             float* As, float* Bs) {
    int tid = threadIdx.x;
    int lane = tid & 31;
    int warp = tid >> 5;
    int wm = (warp & 3) * 32;
    int wn = (warp >> 2) * 64;

    for (int kt = 0; kt < DD; kt += 32) {
#pragma unroll
        for (int p = 0; p < 4; p++) {
            int r = p * 32 + (tid >> 3);
            int c = (tid & 7) * 4;
            *(float4*)(As + r * 36 + c) = *(const float4*)(A + (size_t)(bm + r) * DD + kt + c);
        }
        if (TB) {
#pragma unroll
            for (int p = 0; p < 4; p++) {
                int r = p * 32 + (tid >> 3);
                int c = (tid & 7) * 4;
                *(float4*)(Bs + r * 36 + c) = *(const float4*)(B + (size_t)(bn + r) * DD + kt + c);
            }
        } else {
#pragma unroll
            for (int p = 0; p < 4; p++) {
                int r = tid >> 3;
                int c = p * 32 + (tid & 7) * 4;
                *(float4*)(Bs + r * 132 + c) = *(const float4*)(B + (size_t)(kt + r) * DD + bn + c);
            }
        }
        __syncthreads();
#pragma unroll
        for (int kk = 0; kk < 4; kk++) {
            int k0 = kk * 8;
            unsigned af[2][4], bf[8][2];
#pragma unroll
            for (int mt = 0; mt < 2; mt++) {
                int r = wm + mt * 16 + (lane >> 2);
                int c = k0 + (lane & 3);
                af[mt][0] = f2tf(As[r * 36 + c]);
                af[mt][1] = f2tf(As[(r + 8) * 36 + c]);
                af[mt][2] = f2tf(As[r * 36 + c + 4]);
                af[mt][3] = f2tf(As[(r + 8) * 36 + c + 4]);
            }
#pragma unroll
            for (int nt = 0; nt < 8; nt++) {
                int cc = wn + nt * 8 + (lane >> 2);
                int rr = k0 + (lane & 3);
                if (TB) {
                    bf[nt][0] = f2tf(Bs[cc * 36 + rr]);
                    bf[nt][1] = f2tf(Bs[cc * 36 + rr + 4]);
                } else {
                    bf[nt][0] = f2tf(Bs[rr * 132 + cc]);
                    bf[nt][1] = f2tf(Bs[(rr + 4) * 132 + cc]);
                }
            }
#pragma unroll
            for (int mt = 0; mt < 2; mt++)
#pragma unroll
                for (int nt = 0; nt < 8; nt++)
                    mma_tf32(acc[mt][nt], af[mt][0], af[mt][1], af[mt][2], af[mt][3],
                             bf[nt][0], bf[nt][1]);
        }
        __syncthreads();
    }
}

// ---------------- batched store GEMM ----------------
struct Desc { const float* A; const float* B; const float* A2; const float* B2; const float* Cadd; float* C; };
struct Batch { Desc d[6]; };

__global__ void gemm_store(Batch p, int transB, int dual, int ldc) {
    __shared__ float As[128 * 36];
    __shared__ float Bs[128 * 36];
    Desc d = p.d[blockIdx.z];
    int bm = blockIdx.y * 128;
    int bn = blockIdx.x * 128;

    float acc[2][8][4];
#pragma unroll
    for (int a = 0; a < 2; a++)
#pragma unroll
        for (int b = 0; b < 8; b++)
#pragma unroll
            for (int c = 0; c < 4; c++) acc[a][b][c] = 0.f;

    if (transB) {
        run_mainloop<true>(d.A, d.B, bm, bn, acc, As, Bs);
        if (dual) run_mainloop<true>(d.A2, d.B2, bm, bn, acc, As, Bs);
    } else {
        run_mainloop<false>(d.A, d.B, bm, bn, acc, As, Bs);
        if (dual) run_mainloop<false>(d.A2, d.B2, bm, bn, acc, As, Bs);
    }

    int lane = threadIdx.x & 31;
    int warp = threadIdx.x >> 5;
    int wm = (warp & 3) * 32;
    int wn = (warp >> 2) * 64;
#pragma unroll
    for (int mt = 0; mt < 2; mt++)
#pragma unroll
        for (int half = 0; half < 2; half++) {
            int r = bm + wm + mt * 16 + (lane >> 2) + half * 8;
#pragma unroll
            for (int nt = 0; nt < 8; nt++) {
                int c = bn + wn + nt * 8 + (lane & 3) * 2;
                float2 v;
                v.x = acc[mt][nt][half * 2 + 0];
                v.y = acc[mt][nt][half * 2 + 1];
                if (d.Cadd) {
                    v.x += d.Cadd[(size_t)r * ldc + c];
                    v.y += d.Cadd[(size_t)r * ldc + c + 1];
                }
                *(float2*)(d.C + (size_t)r * ldc + c) = v;
            }
        }
}

// ---------------- E-GEMM with fused logit epilogue ----------------
// t = R @ g_K ; logit_e += scale * [ sum_c (t[e,c] + S1[sbj,c] + S2[obj,c]) * R[e,c]
//                                    + G[sbj,obj] + d1[sbj] + d2[obj] ]   (c3 pre-folded into S1)
__global__ void gemm_logit(const float* __restrict__ R,
                           const int* __restrict__ sbj,
                           const int* __restrict__ obj) {
    __shared__ float As[128 * 36];
    __shared__ float Bs[128 * 36];
    int bm = blockIdx.y * 128;
    int bn = blockIdx.x * 128;

    float acc[2][8][4];
#pragma unroll
    for (int a = 0; a < 2; a++)
#pragma unroll
        for (int b = 0; b < 8; b++)
#pragma unroll
            for (int c = 0; c < 4; c++) acc[a][b][c] = 0.f;

    run_mainloop<false>(R, g_K, bm, bn, acc, As, Bs);

    int lane = threadIdx.x & 31;
    int warp = threadIdx.x >> 5;
    int wm = (warp & 3) * 32;
    int wn = (warp >> 2) * 64;
    const float scale = 0.03125f;  // 1/sqrt(1024)

#pragma unroll
    for (int mt = 0; mt < 2; mt++) {
#pragma unroll
        for (int half = 0; half < 2; half++) {
            int r = bm + wm + mt * 16 + (lane >> 2) + half * 8;
            int s = sbj[r], o = obj[r];
            const float* Rr  = R    + (size_t)r * DD;
            const float* S1r = g_S1 + (size_t)s * DD;
            const float* S2r = g_S2 + (size_t)o * DD;
            float part = 0.f;
#pragma unroll
            for (int nt = 0; nt < 8; nt++) {
                int c = bn + wn + nt * 8 + (lane & 3) * 2;
                float2 Rv  = *(const float2*)(Rr + c);
                float2 s1v = *(const float2*)(S1r + c);
                float2 s2v = *(const float2*)(S2r + c);
                part += (acc[mt][nt][half * 2 + 0] + s1v.x + s2v.x) * Rv.x;
                part += (acc[mt][nt][half * 2 + 1] + s1v.y + s2v.y) * Rv.y;
            }
            part += __shfl_xor_sync(0xFFFFFFFF, part, 1);
            part += __shfl_xor_sync(0xFFFFFFFF, part, 2);
            if ((lane & 3) == 0) {
                if (bn == 0 && (warp >> 2) == 0)
                    part += g_G[(size_t)s * NN + o] + g_d1[s] + g_d2[o];
                atomicAdd(&g_logits[r], part * scale);
            }
        }
    }
}

// ---------------- final vj GEMM ----------------
__global__ void gemm_vj(const float* __restrict__ Wctx,
                        const float* __restrict__ bias,
                        const float* __restrict__ vf,
                        float* __restrict__ out) {
    __shared__ float As[128 * 36];
    __shared__ float Bs[128 * 36];
    int bm = blockIdx.y * 128;
    int bn = blockIdx.x * 128;

    float acc[2][8][4];
#pragma unroll
    for (int a = 0; a < 2; a++)
#pragma unroll
        for (int b = 0; b < 8; b++)
#pragma unroll
            for (int c = 0; c < 4; c++) acc[a][b][c] = 0.f;

    run_mainloop<false>(g_ctx, Wctx, bm, bn, acc, As, Bs);

    int lane = threadIdx.x & 31;
    int warp = threadIdx.x >> 5;
    int wm = (warp & 3) * 32;
    int wn = (warp >> 2) * 64;
#pragma unroll
    for (int mt = 0; mt < 2; mt++)
#pragma unroll
        for (int half = 0; half < 2; half++) {
            int r = bm + wm + mt * 16 + (lane >> 2) + half * 8;
            bool inv = (g_degS[r] + g_degO[r]) > 0;
            const float* vfr = vf + (size_t)r * DD;
            float* outr = out + (size_t)r * DD;
#pragma unroll
            for (int nt = 0; nt < 8; nt++) {
                int c = bn + wn + nt * 8 + (lane & 3) * 2;
                float2 v;
                v.x = vfr[c]     + acc[mt][nt][half * 2 + 0] + (inv ? bias[c] : 0.f);
                v.y = vfr[c + 1] + acc[mt][nt][half * 2 + 1] + (inv ? bias[c + 1] : 0.f);
                *(float2*)(outr + c) = v;
            }
        }
}

// ---------------- small kernels ----------------
__global__ void k_init() {
    int i = blockIdx.x * blockDim.x + threadIdx.x;
    if (i < NN * DD) g_ctx[i] = 0.f;
    if (i < EE) g_logits[i] = 0.f;
    if (i < NN) {
        g_sumS[i] = 0.f; g_sumO[i] = 0.f;
        g_maxS[i] = 0u; g_maxO[i] = 0u;
        g_degS[i] = 0; g_degO[i] = 0;
    }
}
__global__ void k_hist(const int* __restrict__ sbj, const int* __restrict__ obj) {
    int e = blockIdx.x * blockDim.x + threadIdx.x;
    if (e < EE) { atomicAdd(&g_degS[sbj[e]], 1); atomicAdd(&g_degO[obj[e]], 1); }
}
__global__ void k_scan() {
    if (threadIdx.x == 0) {
        int s = 0, o = 0;
        for (int n = 0; n < NN; n++) {
            g_baseS[n] = s; s += g_degS[n];
            g_baseO[n] = o; g_curO[n] = o; o += g_degO[n];
        }
    }
}
__global__ void k_scatter(const int* __restrict__ obj) {
    int e = blockIdx.x * blockDim.x + threadIdx.x;
    if (e < EE) { int p = atomicAdd(&g_curO[obj[e]], 1); g_permO[p] = e; }
}
// cs = b_sbj + b_rel@Ws_r ; co = b_obj + b_rel@Wo_r
__global__ void k_vecs1(const float* __restrict__ b_rel, const float* __restrict__ b_sbj,
                        const float* __restrict__ b_obj, const float* __restrict__ Ws_r,
                        const float* __restrict__ Wo_r) {
    int j = blockIdx.x * blockDim.x + threadIdx.x;
    if (j >= DD) return;
    float s = 0.f, o = 0.f;
    for (int i = 0; i < DD; i++) {
        float br = b_rel[i];
        s += br * Ws_r[(size_t)i * DD + j];
        o += br * Wo_r[(size_t)i * DD + j];
    }
    g_cs[j] = s + b_sbj[j];
    g_co[j] = o + b_obj[j];
}
// c3[j] = sum_i cs[i]*Ho[j,i] + co[i]*Hs[j,i]
__global__ void k_c3() {
    int j = blockIdx.x * 8 + (threadIdx.x >> 5);
    int lane = threadIdx.x & 31;
    if (j >= DD) return;
    float a = 0.f;
    for (int i = lane; i < DD; i += 32)
        a += g_cs[i] * g_Ho[(size_t)j * DD + i] + g_co[i] * g_Hs[(size_t)j * DD + i];
#pragma unroll
    for (int off = 16; off > 0; off >>= 1) a += __shfl_xor_sync(0xFFFFFFFF, a, off);
    if (lane == 0) g_c3[j] = a;
}
__global__ void k_addc3() {
    int i = blockIdx.x * blockDim.x + threadIdx.x;
    if (i < NN * DD) g_S1[i] += g_c3[i & (DD - 1)];
}
// d1[n] = (Ts[n]+cs)·(Uo[n]+co) ; d2[n] = (Us[n]+cs)·(To[n]+co) - cs·co
__global__ void k_scal() {
    int n = blockIdx.x * 8 + (threadIdx.x >> 5);
    int lane = threadIdx.x & 31;
    if (n >= NN) return;
    const float* Ts = g_T + 0 * NN * DD + (size_t)n * DD;
    const float* Us = g_T + 1 * NN * DD + (size_t)n * DD;
    const float* To = g_T + 2 * NN * DD + (size_t)n * DD;
    const float* Uo = g_T + 3 * NN * DD + (size_t)n * DD;
    float t1 = 0.f, t2 = 0.f, t3 = 0.f;
    for (int c = lane; c < DD; c += 32) {
        float cs = g_cs[c], co = g_co[c];
        t1 += (Ts[c] + cs) * (Uo[c] + co);
        t2 += (Us[c] + cs) * (To[c] + co);
        t3 += cs * co;
    }
#pragma unroll
    for (int off = 16; off > 0; off >>= 1) {
        t1 += __shfl_xor_sync(0xFFFFFFFF, t1, off);
        t2 += __shfl_xor_sync(0xFFFFFFFF, t2, off);
        t3 += __shfl_xor_sync(0xFFFFFFFF, t3, off);
    }
    if (lane == 0) { g_d1[n] = t1; g_d2[n] = t2 - t3; }
}
__global__ void k_max(const int* __restrict__ sbj, const int* __restrict__ obj) {
    int e = blockIdx.x * blockDim.x + threadIdx.x;
    if (e < EE) {
        unsigned k = fkey(g_logits[e]);
        atomicMax(&g_maxS[sbj[e]], k);
        atomicMax(&g_maxO[obj[e]], k);
    }
}
__global__ void k_exp(const int* __restrict__ sbj, const int* __restrict__ obj) {
    int e = blockIdx.x * blockDim.x + threadIdx.x;
    if (e < EE) {
        float l = g_logits[e];
        float es = expf(l - funkey(g_maxS[sbj[e]]));
        float eo = expf(l - funkey(g_maxO[obj[e]]));
        g_wS[e] = es; g_wO[e] = eo;
        atomicAdd(&g_sumS[sbj[e]], es);
        atomicAdd(&g_sumO[obj[e]], eo);
    }
}
__global__ void k_norm(const int* __restrict__ sbj, const int* __restrict__ obj) {
    int e = blockIdx.x * blockDim.x + threadIdx.x;
    if (e < EE) {
        g_wS[e] /= g_sumS[sbj[e]];
        g_wO[e] /= g_sumO[obj[e]];
    }
}
__global__ void k_ctxS(const int* __restrict__ obj, const float* __restrict__ vf) {
    int n = blockIdx.x, t = threadIdx.x;
    int beg = g_baseS[n], cnt = g_degS[n];
    if (cnt == 0) return;
    const float4* vf4 = (const float4*)vf;
    float4 acc = make_float4(0.f, 0.f, 0.f, 0.f);
    for (int i = 0; i < cnt; i++) {
        int e = beg + i;
        float w = g_wS[e];
        float4 v = vf4[(size_t)obj[e] * 256 + t];
        acc.x += w * v.x; acc.y += w * v.y; acc.z += w * v.z; acc.w += w * v.w;
    }
    ((float4*)g_ctx)[(size_t)n * 256 + t] = acc;
}
__global__ void k_ctxO(const int* __restrict__ sbj, const float* __restrict__ vf) {
    int n = blockIdx.x, t = threadIdx.x;
    int beg = g_baseO[n], cnt = g_degO[n];
    if (cnt == 0) return;
    const float4* vf4 = (const float4*)vf;
    float4 acc = make_float4(0.f, 0.f, 0.f, 0.f);
    for (int i = 0; i < cnt; i++) {
        int e = g_permO[beg + i];
        float w = g_wO[e];
        float4 v = vf4[(size_t)sbj[e] * 256 + t];
        acc.x += w * v.x; acc.y += w * v.y; acc.z += w * v.z; acc.w += w * v.w;
    }
    float4* c4 = (float4*)g_ctx;
    float4 old = c4[(size_t)n * 256 + t];
    old.x += acc.x; old.y += acc.y; old.z += acc.z; old.w += acc.w;
    c4[(size_t)n * 256 + t] = old;
}

// ---------------- launch ----------------
extern "C" void kernel_launch(void* const* d_in, const int* in_sizes, int n_in,
                              void* d_out, int out_size) {
    const float* vf    = (const float*)d_in[0];
    const float* R     = (const float*)d_in[1];
    const float* W_rel = (const float*)d_in[2];
    const float* b_rel = (const float*)d_in[3];
    const float* W_sbj = (const float*)d_in[4];
    const float* b_sbj = (const float*)d_in[5];
    const float* W_obj = (const float*)d_in[6];
    const float* b_obj = (const float*)d_in[7];
    const float* W_ctx = (const float*)d_in[8];
    const float* b_ctx = (const float*)d_in[9];
    const int* sbj     = (const int*)d_in[10];
    const int* obj     = (const int*)d_in[11];
    float* out = (float*)d_out;

    const float* Wr_s = W_rel;
    const float* Wr_o = W_rel + (size_t)DD * DD;
    const float* Wr_r = W_rel + (size_t)2 * DD * DD;
    const float* Ws_v = W_sbj;
    const float* Ws_r = W_sbj + (size_t)DD * DD;
    const float* Wo_v = W_obj;
    const float* Wo_r = W_obj + (size_t)DD * DD;

    // scratch symbol addresses (host-side view)
    float *pHs, *pHo, *pK, *pM, *pT, *pS1, *pS2, *pG;
    cudaGetSymbolAddress((void**)&pHs, g_Hs);
    cudaGetSymbolAddress((void**)&pHo, g_Ho);
    cudaGetSymbolAddress((void**)&pK,  g_K);
    cudaGetSymbolAddress((void**)&pM,  g_M);
    cudaGetSymbolAddress((void**)&pT,  g_T);
    cudaGetSymbolAddress((void**)&pS1, g_S1);
    cudaGetSymbolAddress((void**)&pS2, g_S2);
    cudaGetSymbolAddress((void**)&pG,  g_G);

    // passthrough
    cudaMemcpyAsync(out, R, (size_t)EE * DD * sizeof(float), cudaMemcpyDeviceToDevice);

    k_init<<<(NN * DD + 255) / 256, 256>>>();
    k_hist<<<(EE + 255) / 256, 256>>>(sbj, obj);
    k_scan<<<1, 32>>>();
    k_scatter<<<(EE + 255) / 256, 256>>>(obj);
    k_vecs1<<<4, 256>>>(b_rel, b_sbj, b_obj, Ws_r, Wo_r);

    // batch 1: 6 weight-weight GEMMs (NN, M=N=K=1024)
    {
        Batch b{};
        b.d[0] = {Wr_r, Ws_r, nullptr, nullptr, nullptr, pHs};
        b.d[1] = {Wr_r, Wo_r, nullptr, nullptr, nullptr, pHo};
        b.d[2] = {Wr_s, Ws_r, nullptr, nullptr, Ws_v,    pM + 0 * (size_t)DD * DD};
        b.d[3] = {Wr_o, Ws_r, nullptr, nullptr, nullptr, pM + 1 * (size_t)DD * DD};
        b.d[4] = {Wr_o, Wo_r, nullptr, nullptr, Wo_v,    pM + 2 * (size_t)DD * DD};
        b.d[5] = {Wr_s, Wo_r, nullptr, nullptr, nullptr, pM + 3 * (size_t)DD * DD};
        gemm_store<<<dim3(8, 8, 6), 256>>>(b, 0, 0, DD);
    }
    // node projections: Ts,Us,To,Uo = vf @ M1..M4 (NN, M=768)
    {
        Batch b{};
        for (int z = 0; z < 4; z++)
            b.d[z] = {vf, pM + (size_t)z * DD * DD, nullptr, nullptr, nullptr, pT + (size_t)z * NN * DD};
        gemm_store<<<dim3(8, 6, 4), 256>>>(b, 0, 0, DD);
    }
    // K = Hs @ Ho^T (NT)
    {
        Batch b{};
        b.d[0] = {pHs, pHo, nullptr, nullptr, nullptr, pK};
        gemm_store<<<dim3(8, 8, 1), 256>>>(b, 1, 0, DD);
    }
    // S1 = Ts@Ho^T + Uo@Hs^T ; S2 = Us@Ho^T + To@Hs^T (dual NT, M=768)
    {
        Batch b{};
        b.d[0] = {pT + 0 * (size_t)NN * DD, pHo, pT + 3 * (size_t)NN * DD, pHs, nullptr, pS1};
        b.d[1] = {pT + 1 * (size_t)NN * DD, pHo, pT + 2 * (size_t)NN * DD, pHs, nullptr, pS2};
        gemm_store<<<dim3(8, 6, 2), 256>>>(b, 1, 1, DD);
    }
    // G = Ts@To^T + Uo@Us^T (dual NT, 768x768)
    {
        Batch b{};
        b.d[0] = {pT + 0 * (size_t)NN * DD, pT + 2 * (size_t)NN * DD,
                  pT + 3 * (size_t)NN * DD, pT + 1 * (size_t)NN * DD, nullptr, pG};
        gemm_store<<<dim3(6, 6, 1), 256>>>(b, 1, 1, NN);
    }
    k_c3<<<128, 256>>>();
    k_addc3<<<(NN * DD + 255) / 256, 256>>>();
    k_scal<<<96, 256>>>();

    // E-GEMM: t = R@K with fused logit epilogue
    gemm_logit<<<dim3(8, 192), 256>>>(R, sbj, obj);

    // dual edge softmax + ctx
    k_max<<<(EE + 255) / 256, 256>>>(sbj, obj);
    k_exp<<<(EE + 255) / 256, 256>>>(sbj, obj);
    k_norm<<<(EE + 255) / 256, 256>>>(sbj, obj);
    k_ctxS<<<NN, 256>>>(obj, vf);
    k_ctxO<<<NN, 256>>>(sbj, vf);

    // vj_out = vf + ctx@W_ctx + b_ctx (involved)
    gemm_vj<<<dim3(8, 6), 256>>>(W_ctx, b_ctx, vf, out + (size_t)EE * DD);

    (void)in_sizes; (void)n_in; (void)out_size;
}

// round 4
// speedup vs baseline: 1.5886x; 1.1630x over previous
#include <cuda_runtime.h>
#include <cuda_bf16.h>
#include <math.h>

#define NN 768
#define EE 24576
#define DD 1024

// ---------------- scratch ----------------
__device__ __align__(128) float g_Hs[DD * DD];
__device__ __align__(128) float g_Ho[DD * DD];
__device__ __align__(128) float g_K [DD * DD];
__device__ __align__(128) float g_M [4 * DD * DD];
__device__ __align__(128) float g_T [4 * NN * DD];
__device__ __align__(128) float g_S1[NN * DD];
__device__ __align__(128) float g_S2[NN * DD];
__device__ __align__(128) float g_G [NN * NN];
__device__ __align__(128) float g_ctx[NN * DD];
__device__ float g_cs[DD], g_co[DD], g_c3[DD];
__device__ float g_d1[NN], g_d2[NN];
__device__ __align__(128) float g_logits[EE];
__device__ __align__(128) float g_wS[EE];
__device__ __align__(128) float g_wO[EE];
__device__ unsigned g_maxS[NN], g_maxO[NN];
__device__ float g_sumS[NN], g_sumO[NN];
__device__ int g_degS[NN], g_degO[NN], g_baseS[NN], g_baseO[NN], g_curO[NN];
__device__ int g_permO[EE];

// smem layout (floats): As = 2 stages * 128*36 ; Bs = 2 stages * max(128*36, 32*132)
#define ASTG (128 * 36)
#define BSTG_TB (128 * 36)
#define BSTG_NT (32 * 132)
#define SMEM_FLOATS (2 * ASTG + 2 * BSTG_TB)
#define SMEM_BYTES (SMEM_FLOATS * 4)

// ---------------- helpers ----------------
__device__ __forceinline__ void mma_tf32(float c[4], unsigned a0, unsigned a1, unsigned a2, unsigned a3,
                                         unsigned b0, unsigned b1) {
    asm volatile(
        "mma.sync.aligned.m16n8k8.row.col.f32.tf32.tf32.f32 "
        "{%0,%1,%2,%3},{%4,%5,%6,%7},{%8,%9},{%0,%1,%2,%3};"
        : "+f"(c[0]), "+f"(c[1]), "+f"(c[2]), "+f"(c[3])
        : "r"(a0), "r"(a1), "r"(a2), "r"(a3), "r"(b0), "r"(b1));
}
__device__ __forceinline__ void cpa16(float* s, const float* g) {
    unsigned sa = (unsigned)__cvta_generic_to_shared(s);
    asm volatile("cp.async.cg.shared.global [%0], [%1], 16;" :: "r"(sa), "l"(g));
}
__device__ __forceinline__ void cpa_commit() { asm volatile("cp.async.commit_group;"); }
template<int N> __device__ __forceinline__ void cpa_wait() { asm volatile("cp.async.wait_group %0;" :: "n"(N)); }

__device__ __forceinline__ unsigned fkey(float f) {
    unsigned u = __float_as_uint(f);
    return (u & 0x80000000u) ? ~u : (u | 0x80000000u);
}
__device__ __forceinline__ float funkey(unsigned k) {
    return (k & 0x80000000u) ? __uint_as_float(k ^ 0x80000000u) : __uint_as_float(~k);
}

// ---------------- pipelined tf32 mainloop (128x128 tile, K=1024, BK=32, 2-stage cp.async) ----------------
template<bool TB>
__device__ __forceinline__ void run_mainloop(const float* __restrict__ A,
                                             const float* __restrict__ B,
                                             int bm, int bn,
                                             float (&acc)[2][8][4],
                                             float* __restrict__ As,
                                             float* __restrict__ Bs) {
    const int BSTG = TB ? BSTG_TB : BSTG_NT;
    int tid = threadIdx.x;
    int lane = tid & 31;
    int warp = tid >> 5;
    int wm = (warp & 3) * 32;
    int wn = (warp >> 2) * 64;

    auto issue = [&](int kt, int stg) {
        float* as = As + stg * ASTG;
        float* bs = Bs + stg * BSTG;
#pragma unroll
        for (int p = 0; p < 4; p++) {
            int r = p * 32 + (tid >> 3);
            int c = (tid & 7) * 4;
            cpa16(as + r * 36 + c, A + (size_t)(bm + r) * DD + kt * 32 + c);
        }
        if (TB) {
#pragma unroll
            for (int p = 0; p < 4; p++) {
                int r = p * 32 + (tid >> 3);
                int c = (tid & 7) * 4;
                cpa16(bs + r * 36 + c, B + (size_t)(bn + r) * DD + kt * 32 + c);
            }
        } else {
#pragma unroll
            for (int p = 0; p < 4; p++) {
                int r = tid >> 3;
                int c = p * 32 + (tid & 7) * 4;
                cpa16(bs + r * 132 + c, B + (size_t)(kt * 32 + r) * DD + bn + c);
            }
        }
        cpa_commit();
    };

    issue(0, 0);
    for (int kt = 0; kt < 32; kt++) {
        if (kt + 1 < 32) { issue(kt + 1, (kt + 1) & 1); cpa_wait<1>(); }
        else cpa_wait<0>();
        __syncthreads();
        const float* as = As + (kt & 1) * ASTG;
        const float* bs = Bs + (kt & 1) * BSTG;
#pragma unroll
        for (int kk = 0; kk < 4; kk++) {
            int k0 = kk * 8;
            unsigned af[2][4], bf[8][2];
#pragma unroll
            for (int mt = 0; mt < 2; mt++) {
                int r = wm + mt * 16 + (lane >> 2);
                int c = k0 + (lane & 3);
                af[mt][0] = __float_as_uint(as[r * 36 + c]);
                af[mt][1] = __float_as_uint(as[(r + 8) * 36 + c]);
                af[mt][2] = __float_as_uint(as[r * 36 + c + 4]);
                af[mt][3] = __float_as_uint(as[(r + 8) * 36 + c + 4]);
            }
#pragma unroll
            for (int nt = 0; nt < 8; nt++) {
                int cc = wn + nt * 8 + (lane >> 2);
                int rr = k0 + (lane & 3);
                if (TB) {
                    bf[nt][0] = __float_as_uint(bs[cc * 36 + rr]);
                    bf[nt][1] = __float_as_uint(bs[cc * 36 + rr + 4]);
                } else {
                    bf[nt][0] = __float_as_uint(bs[rr * 132 + cc]);
                    bf[nt][1] = __float_as_uint(bs[(rr + 4) * 132 + cc]);
                }
            }
#pragma unroll
            for (int mt = 0; mt < 2; mt++)
#pragma unroll
                for (int nt = 0; nt < 8; nt++)
                    mma_tf32(acc[mt][nt], af[mt][0], af[mt][1], af[mt][2], af[mt][3],
                             bf[nt][0], bf[nt][1]);
        }
        __syncthreads();
    }
}

// ---------------- batched store GEMM ----------------
struct Desc { const float* A; const float* B; const float* A2; const float* B2; const float* Cadd; float* C; };
struct Batch { Desc d[6]; };

__global__ __launch_bounds__(256) void gemm_store(Batch p, int transB, int dual, int ldc) {
    extern __shared__ float sm[];
    float* As = sm;
    float* Bs = sm + 2 * ASTG;
    Desc d = p.d[blockIdx.z];
    int bm = blockIdx.y * 128;
    int bn = blockIdx.x * 128;

    float acc[2][8][4];
#pragma unroll
    for (int a = 0; a < 2; a++)
#pragma unroll
        for (int b = 0; b < 8; b++)
#pragma unroll
            for (int c = 0; c < 4; c++) acc[a][b][c] = 0.f;

    if (transB) {
        run_mainloop<true>(d.A, d.B, bm, bn, acc, As, Bs);
        if (dual) { __syncthreads(); run_mainloop<true>(d.A2, d.B2, bm, bn, acc, As, Bs); }
    } else {
        run_mainloop<false>(d.A, d.B, bm, bn, acc, As, Bs);
        if (dual) { __syncthreads(); run_mainloop<false>(d.A2, d.B2, bm, bn, acc, As, Bs); }
    }

    int lane = threadIdx.x & 31;
    int warp = threadIdx.x >> 5;
    int wm = (warp & 3) * 32;
    int wn = (warp >> 2) * 64;
#pragma unroll
    for (int mt = 0; mt < 2; mt++)
#pragma unroll
        for (int half = 0; half < 2; half++) {
            int r = bm + wm + mt * 16 + (lane >> 2) + half * 8;
#pragma unroll
            for (int nt = 0; nt < 8; nt++) {
                int c = bn + wn + nt * 8 + (lane & 3) * 2;
                float2 v;
                v.x = acc[mt][nt][half * 2 + 0];
                v.y = acc[mt][nt][half * 2 + 1];
                if (d.Cadd) {
                    v.x += d.Cadd[(size_t)r * ldc + c];
                    v.y += d.Cadd[(size_t)r * ldc + c + 1];
                }
                *(float2*)(d.C + (size_t)r * ldc + c) = v;
            }
        }
}

// ---------------- E-GEMM with fused logit epilogue ----------------
__global__ __launch_bounds__(256) void gemm_logit(const float* __restrict__ R,
                                                  const int* __restrict__ sbj,
                                                  const int* __restrict__ obj) {
    extern __shared__ float sm[];
    float* As = sm;
    float* Bs = sm + 2 * ASTG;
    int bm = blockIdx.y * 128;
    int bn = blockIdx.x * 128;

    float acc[2][8][4];
#pragma unroll
    for (int a = 0; a < 2; a++)
#pragma unroll
        for (int b = 0; b < 8; b++)
#pragma unroll
            for (int c = 0; c < 4; c++) acc[a][b][c] = 0.f;

    run_mainloop<false>(R, g_K, bm, bn, acc, As, Bs);

    int lane = threadIdx.x & 31;
    int warp = threadIdx.x >> 5;
    int wm = (warp & 3) * 32;
    int wn = (warp >> 2) * 64;
    const float scale = 0.03125f;

#pragma unroll
    for (int mt = 0; mt < 2; mt++) {
#pragma unroll
        for (int half = 0; half < 2; half++) {
            int r = bm + wm + mt * 16 + (lane >> 2) + half * 8;
            int s = sbj[r], o = obj[r];
            const float* Rr  = R    + (size_t)r * DD;
            const float* S1r = g_S1 + (size_t)s * DD;
            const float* S2r = g_S2 + (size_t)o * DD;
            float part = 0.f;
#pragma unroll
            for (int nt = 0; nt < 8; nt++) {
                int c = bn + wn + nt * 8 + (lane & 3) * 2;
                float2 Rv  = *(const float2*)(Rr + c);
                float2 s1v = *(const float2*)(S1r + c);
                float2 s2v = *(const float2*)(S2r + c);
                part += (acc[mt][nt][half * 2 + 0] + s1v.x + s2v.x) * Rv.x;
                part += (acc[mt][nt][half * 2 + 1] + s1v.y + s2v.y) * Rv.y;
            }
            part += __shfl_xor_sync(0xFFFFFFFF, part, 1);
            part += __shfl_xor_sync(0xFFFFFFFF, part, 2);
            if ((lane & 3) == 0) {
                if (bn == 0 && (warp >> 2) == 0)
                    part += g_G[(size_t)s * NN + o] + g_d1[s] + g_d2[o];
                atomicAdd(&g_logits[r], part * scale);
            }
        }
    }
}

// ---------------- final vj GEMM ----------------
__global__ __launch_bounds__(256) void gemm_vj(const float* __restrict__ Wctx,
                                               const float* __restrict__ bias,
                                               const float* __restrict__ vf,
                                               float* __restrict__ out) {
    extern __shared__ float sm[];
    float* As = sm;
    float* Bs = sm + 2 * ASTG;
    int bm = blockIdx.y * 128;
    int bn = blockIdx.x * 128;

    float acc[2][8][4];
#pragma unroll
    for (int a = 0; a < 2; a++)
#pragma unroll
        for (int b = 0; b < 8; b++)
#pragma unroll
            for (int c = 0; c < 4; c++) acc[a][b][c] = 0.f;

    run_mainloop<false>(g_ctx, Wctx, bm, bn, acc, As, Bs);

    int lane = threadIdx.x & 31;
    int warp = threadIdx.x >> 5;
    int wm = (warp & 3) * 32;
    int wn = (warp >> 2) * 64;
#pragma unroll
    for (int mt = 0; mt < 2; mt++)
#pragma unroll
        for (int half = 0; half < 2; half++) {
            int r = bm + wm + mt * 16 + (lane >> 2) + half * 8;
            bool inv = (g_degS[r] + g_degO[r]) > 0;
            const float* vfr = vf + (size_t)r * DD;
            float* outr = out + (size_t)r * DD;
#pragma unroll
            for (int nt = 0; nt < 8; nt++) {
                int c = bn + wn + nt * 8 + (lane & 3) * 2;
                float2 v;
                v.x = vfr[c]     + acc[mt][nt][half * 2 + 0] + (inv ? bias[c] : 0.f);
                v.y = vfr[c + 1] + acc[mt][nt][half * 2 + 1] + (inv ? bias[c + 1] : 0.f);
                *(float2*)(outr + c) = v;
            }
        }
}

// ---------------- small kernels ----------------
__global__ void k_init() {
    int i = blockIdx.x * blockDim.x + threadIdx.x;
    if (i < NN * DD) g_ctx[i] = 0.f;
    if (i < EE) g_logits[i] = 0.f;
    if (i < NN) {
        g_sumS[i] = 0.f; g_sumO[i] = 0.f;
        g_maxS[i] = 0u; g_maxO[i] = 0u;
        g_degS[i] = 0; g_degO[i] = 0;
    }
}
__global__ void k_hist(const int* __restrict__ sbj, const int* __restrict__ obj) {
    int e = blockIdx.x * blockDim.x + threadIdx.x;
    if (e < EE) { atomicAdd(&g_degS[sbj[e]], 1); atomicAdd(&g_degO[obj[e]], 1); }
}
__global__ void k_scan() {
    if (threadIdx.x == 0) {
        int s = 0, o = 0;
        for (int n = 0; n < NN; n++) {
            g_baseS[n] = s; s += g_degS[n];
            g_baseO[n] = o; g_curO[n] = o; o += g_degO[n];
        }
    }
}
__global__ void k_scatter(const int* __restrict__ obj) {
    int e = blockIdx.x * blockDim.x + threadIdx.x;
    if (e < EE) { int p = atomicAdd(&g_curO[obj[e]], 1); g_permO[p] = e; }
}
__global__ void k_vecs1(const float* __restrict__ b_rel, const float* __restrict__ b_sbj,
                        const float* __restrict__ b_obj, const float* __restrict__ Ws_r,
                        const float* __restrict__ Wo_r) {
    int j = blockIdx.x * blockDim.x + threadIdx.x;
    if (j >= DD) return;
    float s = 0.f, o = 0.f;
    for (int i = 0; i < DD; i++) {
        float br = b_rel[i];
        s += br * Ws_r[(size_t)i * DD + j];
        o += br * Wo_r[(size_t)i * DD + j];
    }
    g_cs[j] = s + b_sbj[j];
    g_co[j] = o + b_obj[j];
}
__global__ void k_c3() {
    int j = blockIdx.x * 8 + (threadIdx.x >> 5);
    int lane = threadIdx.x & 31;
    if (j >= DD) return;
    float a = 0.f;
    for (int i = lane; i < DD; i += 32)
        a += g_cs[i] * g_Ho[(size_t)j * DD + i] + g_co[i] * g_Hs[(size_t)j * DD + i];
#pragma unroll
    for (int off = 16; off > 0; off >>= 1) a += __shfl_xor_sync(0xFFFFFFFF, a, off);
    if (lane == 0) g_c3[j] = a;
}
__global__ void k_addc3() {
    int i = blockIdx.x * blockDim.x + threadIdx.x;
    if (i < NN * DD) g_S1[i] += g_c3[i & (DD - 1)];
}
__global__ void k_scal() {
    int n = blockIdx.x * 8 + (threadIdx.x >> 5);
    int lane = threadIdx.x & 31;
    if (n >= NN) return;
    const float* Ts = g_T + 0 * NN * DD + (size_t)n * DD;
    const float* Us = g_T + 1 * NN * DD + (size_t)n * DD;
    const float* To = g_T + 2 * NN * DD + (size_t)n * DD;
    const float* Uo = g_T + 3 * NN * DD + (size_t)n * DD;
    float t1 = 0.f, t2 = 0.f, t3 = 0.f;
    for (int c = lane; c < DD; c += 32) {
        float cs = g_cs[c], co = g_co[c];
        t1 += (Ts[c] + cs) * (Uo[c] + co);
        t2 += (Us[c] + cs) * (To[c] + co);
        t3 += cs * co;
    }
#pragma unroll
    for (int off = 16; off > 0; off >>= 1) {
        t1 += __shfl_xor_sync(0xFFFFFFFF, t1, off);
        t2 += __shfl_xor_sync(0xFFFFFFFF, t2, off);
        t3 += __shfl_xor_sync(0xFFFFFFFF, t3, off);
    }
    if (lane == 0) { g_d1[n] = t1; g_d2[n] = t2 - t3; }
}
__global__ void k_max(const int* __restrict__ sbj, const int* __restrict__ obj) {
    int e = blockIdx.x * blockDim.x + threadIdx.x;
    if (e < EE) {
        unsigned k = fkey(g_logits[e]);
        atomicMax(&g_maxS[sbj[e]], k);
        atomicMax(&g_maxO[obj[e]], k);
    }
}
__global__ void k_exp(const int* __restrict__ sbj, const int* __restrict__ obj) {
    int e = blockIdx.x * blockDim.x + threadIdx.x;
    if (e < EE) {
        float l = g_logits[e];
        float es = expf(l - funkey(g_maxS[sbj[e]]));
        float eo = expf(l - funkey(g_maxO[obj[e]]));
        g_wS[e] = es; g_wO[e] = eo;
        atomicAdd(&g_sumS[sbj[e]], es);
        atomicAdd(&g_sumO[obj[e]], eo);
    }
}
// ctx kernels fold the 1/sum normalization (k_norm eliminated)
__global__ void k_ctxS(const int* __restrict__ obj, const float* __restrict__ vf) {
    int n = blockIdx.x, t = threadIdx.x;
    int beg = g_baseS[n], cnt = g_degS[n];
    if (cnt == 0) return;
    float inv = 1.f / g_sumS[n];
    const float4* vf4 = (const float4*)vf;
    float4 acc = make_float4(0.f, 0.f, 0.f, 0.f);
    for (int i = 0; i < cnt; i++) {
        int e = beg + i;
        float w = g_wS[e];
        float4 v = vf4[(size_t)obj[e] * 256 + t];
        acc.x += w * v.x; acc.y += w * v.y; acc.z += w * v.z; acc.w += w * v.w;
    }
    acc.x *= inv; acc.y *= inv; acc.z *= inv; acc.w *= inv;
    ((float4*)g_ctx)[(size_t)n * 256 + t] = acc;
}
__global__ void k_ctxO(const int* __restrict__ sbj, const float* __restrict__ vf) {
    int n = blockIdx.x, t = threadIdx.x;
    int beg = g_baseO[n], cnt = g_degO[n];
    if (cnt == 0) return;
    float inv = 1.f / g_sumO[n];
    const float4* vf4 = (const float4*)vf;
    float4 acc = make_float4(0.f, 0.f, 0.f, 0.f);
    for (int i = 0; i < cnt; i++) {
        int e = g_permO[beg + i];
        float w = g_wO[e];
        float4 v = vf4[(size_t)sbj[e] * 256 + t];
        acc.x += w * v.x; acc.y += w * v.y; acc.z += w * v.z; acc.w += w * v.w;
    }
    float4* c4 = (float4*)g_ctx;
    float4 old = c4[(size_t)n * 256 + t];
    old.x += acc.x * inv; old.y += acc.y * inv; old.z += acc.z * inv; old.w += acc.w * inv;
    c4[(size_t)n * 256 + t] = old;
}

// ---------------- launch ----------------
extern "C" void kernel_launch(void* const* d_in, const int* in_sizes, int n_in,
                              void* d_out, int out_size) {
    const float* vf    = (const float*)d_in[0];
    const float* R     = (const float*)d_in[1];
    const float* W_rel = (const float*)d_in[2];
    const float* b_rel = (const float*)d_in[3];
    const float* W_sbj = (const float*)d_in[4];
    const float* b_sbj = (const float*)d_in[5];
    const float* W_obj = (const float*)d_in[6];
    const float* b_obj = (const float*)d_in[7];
    const float* W_ctx = (const float*)d_in[8];
    const float* b_ctx = (const float*)d_in[9];
    const int* sbj     = (const int*)d_in[10];
    const int* obj     = (const int*)d_in[11];
    float* out = (float*)d_out;

    const float* Wr_s = W_rel;
    const float* Wr_o = W_rel + (size_t)DD * DD;
    const float* Wr_r = W_rel + (size_t)2 * DD * DD;
    const float* Ws_v = W_sbj;
    const float* Ws_r = W_sbj + (size_t)DD * DD;
    const float* Wo_v = W_obj;
    const float* Wo_r = W_obj + (size_t)DD * DD;

    // Unconditional (idempotent, not a stream op, deterministic every call).
    cudaFuncSetAttribute(gemm_store, cudaFuncAttributeMaxDynamicSharedMemorySize, SMEM_BYTES);
    cudaFuncSetAttribute(gemm_logit, cudaFuncAttributeMaxDynamicSharedMemorySize, SMEM_BYTES);
    cudaFuncSetAttribute(gemm_vj,    cudaFuncAttributeMaxDynamicSharedMemorySize, SMEM_BYTES);

    float *pHs, *pHo, *pK, *pM, *pT, *pS1, *pS2, *pG;
    cudaGetSymbolAddress((void**)&pHs, g_Hs);
    cudaGetSymbolAddress((void**)&pHo, g_Ho);
    cudaGetSymbolAddress((void**)&pK,  g_K);
    cudaGetSymbolAddress((void**)&pM,  g_M);
    cudaGetSymbolAddress((void**)&pT,  g_T);
    cudaGetSymbolAddress((void**)&pS1, g_S1);
    cudaGetSymbolAddress((void**)&pS2, g_S2);
    cudaGetSymbolAddress((void**)&pG,  g_G);

    cudaMemcpyAsync(out, R, (size_t)EE * DD * sizeof(float), cudaMemcpyDeviceToDevice);

    k_init<<<(NN * DD + 255) / 256, 256>>>();
    k_hist<<<(EE + 255) / 256, 256>>>(sbj, obj);
    k_scan<<<1, 32>>>();
    k_scatter<<<(EE + 255) / 256, 256>>>(obj);
    k_vecs1<<<4, 256>>>(b_rel, b_sbj, b_obj, Ws_r, Wo_r);

    {
        Batch b{};
        b.d[0] = {Wr_r, Ws_r, nullptr, nullptr, nullptr, pHs};
        b.d[1] = {Wr_r, Wo_r, nullptr, nullptr, nullptr, pHo};
        b.d[2] = {Wr_s, Ws_r, nullptr, nullptr, Ws_v,    pM + 0 * (size_t)DD * DD};
        b.d[3] = {Wr_o, Ws_r, nullptr, nullptr, nullptr, pM + 1 * (size_t)DD * DD};
        b.d[4] = {Wr_o, Wo_r, nullptr, nullptr, Wo_v,    pM + 2 * (size_t)DD * DD};
        b.d[5] = {Wr_s, Wo_r, nullptr, nullptr, nullptr, pM + 3 * (size_t)DD * DD};
        gemm_store<<<dim3(8, 8, 6), 256, SMEM_BYTES>>>(b, 0, 0, DD);
    }
    {
        Batch b{};
        for (int z = 0; z < 4; z++)
            b.d[z] = {vf, pM + (size_t)z * DD * DD, nullptr, nullptr, nullptr, pT + (size_t)z * NN * DD};
        gemm_store<<<dim3(8, 6, 4), 256, SMEM_BYTES>>>(b, 0, 0, DD);
    }
    {
        Batch b{};
        b.d[0] = {pHs, pHo, nullptr, nullptr, nullptr, pK};
        gemm_store<<<dim3(8, 8, 1), 256, SMEM_BYTES>>>(b, 1, 0, DD);
    }
    {
        Batch b{};
        b.d[0] = {pT + 0 * (size_t)NN * DD, pHo, pT + 3 * (size_t)NN * DD, pHs, nullptr, pS1};
        b.d[1] = {pT + 1 * (size_t)NN * DD, pHo, pT + 2 * (size_t)NN * DD, pHs, nullptr, pS2};
        gemm_store<<<dim3(8, 6, 2), 256, SMEM_BYTES>>>(b, 1, 1, DD);
    }
    {
        Batch b{};
        b.d[0] = {pT + 0 * (size_t)NN * DD, pT + 2 * (size_t)NN * DD,
                  pT + 3 * (size_t)NN * DD, pT + 1 * (size_t)NN * DD, nullptr, pG};
        gemm_store<<<dim3(6, 6, 1), 256, SMEM_BYTES>>>(b, 1, 1, NN);
    }
    k_c3<<<128, 256>>>();
    k_addc3<<<(NN * DD + 255) / 256, 256>>>();
    k_scal<<<96, 256>>>();

    gemm_logit<<<dim3(8, 192), 256, SMEM_BYTES>>>(R, sbj, obj);

    k_max<<<(EE + 255) / 256, 256>>>(sbj, obj);
    k_exp<<<(EE + 255) / 256, 256>>>(sbj, obj);
    k_ctxS<<<NN, 256>>>(obj, vf);
    k_ctxO<<<NN, 256>>>(sbj, vf);

    gemm_vj<<<dim3(8, 6), 256, SMEM_BYTES>>>(W_ctx, b_ctx, vf, out + (size_t)EE * DD);

    (void)in_sizes; (void)n_in; (void)out_size;
}